// round 1
// baseline (speedup 1.0000x reference)
#include <cuda_runtime.h>
#include <math.h>

#define B_  16
#define L_  4096
#define E_  128
#define F_  256
#define KW_ 3
#define Y_  1000
#define EK_ (E_ * KW_)   /* 384 */
#define M2_ (2 * Y_)     /* 2000 */

// Scratch (static __device__ arrays; allocation-free per harness rules)
__device__ float g_col[(size_t)B_ * EK_ * L_];   // im2col, ~100 MB
__device__ float g_hc [(size_t)B_ * F_  * L_];   // conv out, ~67 MB
__device__ float g_st [(size_t)B_ * M2_ * L_];   // scores(0..999) / t(1000..1999), ~524 MB

// ---------------------------------------------------------------------------
// Kernel 1: fused embedding lookup + im2col scatter.
// col[b][e*3+k][l'] = embed_w[x[b][l'+k-1]][e]  (zero outside [0,L))
// Each thread owns one source position l and scatters its embedding row to the
// three shifted (k) destinations: l' = l+1-k.
// ---------------------------------------------------------------------------
__global__ void embed_im2col_kernel(const int* __restrict__ x,
                                    const float* __restrict__ embed_w)
{
    int b = blockIdx.y;
    int l = blockIdx.x * blockDim.x + threadIdx.x;
    if (l >= L_) return;

    int xi = x[b * L_ + l];
    const float4* er4 = (const float4*)(embed_w + (size_t)xi * E_);
    float* colb = g_col + (size_t)b * EK_ * L_;

    #pragma unroll 4
    for (int e4 = 0; e4 < E_ / 4; e4++) {
        float4 v = er4[e4];
        float vv[4] = {v.x, v.y, v.z, v.w};
        #pragma unroll
        for (int q = 0; q < 4; q++) {
            int e = e4 * 4 + q;
            float val = vv[q];
            float* base = colb + (size_t)(e * 3) * L_;
            // k=0 -> l' = l+1 ; k=1 -> l' = l ; k=2 -> l' = l-1
            if (l + 1 < L_) base[0 * L_ + (l + 1)] = val;
            base[1 * L_ + l] = val;
            if (l >= 1)     base[2 * L_ + (l - 1)] = val;
            // boundary zeros (positions whose source is out of range)
            if (l == 0)      base[0 * L_ + 0] = 0.0f;
            if (l == L_ - 1) base[2 * L_ + (L_ - 1)] = 0.0f;
        }
    }
}

// ---------------------------------------------------------------------------
// Kernel 2/3: fp32 register-tiled GEMM, C = A @ B per batch, optional bias+relu.
// Tile 128x128, BK=8, 256 threads, 8x8 micro-tile per thread.
// A rows come from A0 (rows [0,A0rows)) then A1 (rows [A0rows,M)).
// mode 0: B = g_col, C = g_hc     (conv:  M=256,  K=384, relu+bias)
// mode 1: B = g_hc,  C = g_st     (attn:  M=2000, K=256)
// ---------------------------------------------------------------------------
#define BM 128
#define BN 128
#define BK 8

__global__ __launch_bounds__(256, 2)
void gemm128_kernel(const float* __restrict__ A0, const float* __restrict__ A1,
                    int A0rows, const float* __restrict__ bias,
                    int M, int K, int mode, int fuse_relu)
{
    const int N = L_;
    const float* Bg = (mode == 0) ? g_col : g_hc;
    float*       Cg = (mode == 0) ? g_hc  : g_st;
    const float* Bb = Bg + (size_t)blockIdx.z * K * N;
    float*       Cb = Cg + (size_t)blockIdx.z * (size_t)M * N;

    int m0 = blockIdx.y * BM;
    int n0 = blockIdx.x * BN;
    int tid = threadIdx.x;

    __shared__ __align__(16) float As[BK][BM + 4];
    __shared__ __align__(16) float Bs[BK][BN];

    float acc[8][8];
    #pragma unroll
    for (int i = 0; i < 8; i++)
        #pragma unroll
        for (int j = 0; j < 8; j++) acc[i][j] = 0.0f;

    int ty = tid >> 4, tx = tid & 15;

    // A tile load mapping: 128 rows x 8 cols = 1024 elems, float4 per thread
    int arow = tid >> 1;
    int ak4  = (tid & 1) * 4;
    // B tile load mapping: 8 rows x 128 cols
    int brow  = tid >> 5;
    int bcol4 = (tid & 31) * 4;

    for (int k0 = 0; k0 < K; k0 += BK) {
        // ---- load A tile (transposed into As[k][m]) ----
        int m = m0 + arow;
        float4 av = make_float4(0.f, 0.f, 0.f, 0.f);
        if (m < M) {
            const float* Ap = (m < A0rows) ? (A0 + (size_t)m * K)
                                           : (A1 + (size_t)(m - A0rows) * K);
            av = *(const float4*)(Ap + k0 + ak4);
        }
        As[ak4 + 0][arow] = av.x;
        As[ak4 + 1][arow] = av.y;
        As[ak4 + 2][arow] = av.z;
        As[ak4 + 3][arow] = av.w;

        // ---- load B tile ----
        float4 bv = *(const float4*)(Bb + (size_t)(k0 + brow) * N + n0 + bcol4);
        *(float4*)&Bs[brow][bcol4] = bv;

        __syncthreads();

        #pragma unroll
        for (int kk = 0; kk < BK; kk++) {
            float a[8], bb[8];
            #pragma unroll
            for (int i = 0; i < 8; i++) a[i]  = As[kk][ty * 8 + i];
            #pragma unroll
            for (int j = 0; j < 8; j++) bb[j] = Bs[kk][tx * 8 + j];
            #pragma unroll
            for (int i = 0; i < 8; i++)
                #pragma unroll
                for (int j = 0; j < 8; j++)
                    acc[i][j] += a[i] * bb[j];
        }
        __syncthreads();
    }

    // ---- epilogue ----
    #pragma unroll
    for (int i = 0; i < 8; i++) {
        int m = m0 + ty * 8 + i;
        if (m < M) {
            float bi = bias ? bias[m] : 0.0f;
            float* crow = Cb + (size_t)m * N + n0 + tx * 8;
            #pragma unroll
            for (int j = 0; j < 8; j += 4) {
                float4 v;
                v.x = acc[i][j + 0] + bi;
                v.y = acc[i][j + 1] + bi;
                v.z = acc[i][j + 2] + bi;
                v.w = acc[i][j + 3] + bi;
                if (fuse_relu) {
                    v.x = fmaxf(v.x, 0.f); v.y = fmaxf(v.y, 0.f);
                    v.z = fmaxf(v.z, 0.f); v.w = fmaxf(v.w, 0.f);
                }
                *(float4*)(crow + j) = v;
            }
        }
    }
}

// ---------------------------------------------------------------------------
// Kernel 4: per-(b,y) online softmax over L + weighted sum of t -> logit.
// logit[b,y] = sum_l softmax(s)[l] * t[l] + fc_b[y]
// ---------------------------------------------------------------------------
__global__ void attn_reduce_kernel(const float* __restrict__ fc_b,
                                   float* __restrict__ out_logit)
{
    int y = blockIdx.x;
    int b = blockIdx.y;
    const float* s = g_st + ((size_t)b * M2_ + y) * L_;
    const float* t = g_st + ((size_t)b * M2_ + Y_ + y) * L_;

    float m = -1e30f, Z = 0.0f, S = 0.0f;
    for (int l = threadIdx.x; l < L_; l += blockDim.x) {
        float sv = s[l], tv = t[l];
        if (sv > m) {
            float r = expf(m - sv);
            Z *= r; S *= r; m = sv;
        }
        float e = expf(sv - m);
        Z += e; S += e * tv;
    }

    // warp merge of (m, Z, S)
    #pragma unroll
    for (int off = 16; off; off >>= 1) {
        float m2 = __shfl_xor_sync(0xFFFFFFFFu, m, off);
        float Z2 = __shfl_xor_sync(0xFFFFFFFFu, Z, off);
        float S2 = __shfl_xor_sync(0xFFFFFFFFu, S, off);
        float mn = fmaxf(m, m2);
        float r1 = expf(m - mn), r2 = expf(m2 - mn);
        Z = Z * r1 + Z2 * r2;
        S = S * r1 + S2 * r2;
        m = mn;
    }

    __shared__ float sm[8], sz[8], ss[8];
    int lane = threadIdx.x & 31, w = threadIdx.x >> 5;
    if (lane == 0) { sm[w] = m; sz[w] = Z; ss[w] = S; }
    __syncthreads();
    if (threadIdx.x == 0) {
        m = sm[0]; Z = sz[0]; S = ss[0];
        int nw = blockDim.x >> 5;
        for (int i = 1; i < nw; i++) {
            float mn = fmaxf(m, sm[i]);
            float r1 = expf(m - mn), r2 = expf(sm[i] - mn);
            Z = Z * r1 + sz[i] * r2;
            S = S * r1 + ss[i] * r2;
            m = mn;
        }
        out_logit[b * Y_ + y] = S / Z + fc_b[y];
    }
}

// ---------------------------------------------------------------------------
// Kernel 5: cross-entropy loss over logits -> out[16000]
// ---------------------------------------------------------------------------
__global__ void loss_kernel(const float* __restrict__ logit,
                            const int* __restrict__ target,
                            float* __restrict__ loss_out)
{
    __shared__ float red[256];
    int tid = threadIdx.x;
    float total = 0.0f;
    for (int b = 0; b < B_; b++) {
        const float* lr = logit + b * Y_;
        float mx = -1e30f;
        for (int i = tid; i < Y_; i += 256) mx = fmaxf(mx, lr[i]);
        red[tid] = mx; __syncthreads();
        for (int s = 128; s; s >>= 1) {
            if (tid < s) red[tid] = fmaxf(red[tid], red[tid + s]);
            __syncthreads();
        }
        mx = red[0]; __syncthreads();

        float se = 0.0f;
        for (int i = tid; i < Y_; i += 256) se += expf(lr[i] - mx);
        red[tid] = se; __syncthreads();
        for (int s = 128; s; s >>= 1) {
            if (tid < s) red[tid] += red[tid + s];
            __syncthreads();
        }
        if (tid == 0) {
            float lp = lr[target[b]] - mx - logf(red[0]);
            total += -lp;
        }
        __syncthreads();
    }
    if (tid == 0) loss_out[0] = total / (float)B_;
}

// ---------------------------------------------------------------------------
extern "C" void kernel_launch(void* const* d_in, const int* in_sizes, int n_in,
                              void* d_out, int out_size)
{
    const int*   x       = (const int*)  d_in[0];
    const int*   target  = (const int*)  d_in[1];
    const float* embed_w = (const float*)d_in[2];
    const float* conv_w  = (const float*)d_in[3];
    const float* conv_b  = (const float*)d_in[4];
    const float* U_w     = (const float*)d_in[5];
    const float* fc_w    = (const float*)d_in[6];
    const float* fc_b    = (const float*)d_in[7];
    float* out = (float*)d_out;   // [0..15999] logits, [16000] loss

    // 1) embedding + im2col
    embed_im2col_kernel<<<dim3(L_ / 256, B_), 256>>>(x, embed_w);

    // 2) conv GEMM: hc = relu(conv_w(256x384) @ col(384x4096) + conv_b)
    gemm128_kernel<<<dim3(L_ / BN, (F_ + BM - 1) / BM, B_), 256>>>(
        conv_w, nullptr, F_, conv_b, F_, EK_, /*mode=*/0, /*relu=*/1);

    // 3) attention GEMM: st = [U_w; fc_w](2000x256) @ hc(256x4096)
    gemm128_kernel<<<dim3(L_ / BN, (M2_ + BM - 1) / BM, B_), 256>>>(
        U_w, fc_w, Y_, nullptr, M2_, F_, /*mode=*/1, /*relu=*/0);

    // 4) softmax-attend reduction -> logits
    attn_reduce_kernel<<<dim3(Y_, B_), 256>>>(fc_b, out);

    // 5) cross-entropy loss -> out[16000]
    loss_kernel<<<1, 256>>>(out, target, out + B_ * Y_);
}

// round 3
// speedup vs baseline: 2.1636x; 2.1636x over previous
#include <cuda_runtime.h>
#include <math.h>

#define B_  16
#define L_  4096
#define E_  128
#define F_  256
#define Y_  1000
#define MP_ 2048             /* padded attn M (2000 -> 2048) */

#define BM  128
#define BN  128
#define BKC 32               /* K chunk (fp32 elems) */

// Scratch (static __device__ arrays; allocation-free per harness rules)
__device__ float g_embT[(size_t)B_ * L_ * E_];   // embedding gather, ~33 MB
__device__ float g_wT  [3 * F_ * E_];            // conv_w transposed [kw][f][e]
__device__ float g_hcT [(size_t)B_ * L_ * F_];   // conv out, [b][l][f], ~67 MB
__device__ float g_st  [(size_t)B_ * MP_ * L_];  // scores rows [0,1000), t rows [1000,2000)

// ---------------------------------------------------------------------------
__device__ __forceinline__ unsigned to_tf32(float x) {
    unsigned r;
    asm("cvt.rna.tf32.f32 %0, %1;" : "=r"(r) : "f"(x));
    return r;
}
__device__ __forceinline__ void mma_tf32(float* d, const unsigned* a, const unsigned* b) {
    asm volatile(
        "mma.sync.aligned.m16n8k8.row.col.f32.tf32.tf32.f32 "
        "{%0,%1,%2,%3}, {%4,%5,%6,%7}, {%8,%9}, {%0,%1,%2,%3};"
        : "+f"(d[0]), "+f"(d[1]), "+f"(d[2]), "+f"(d[3])
        : "r"(a[0]), "r"(a[1]), "r"(a[2]), "r"(a[3]), "r"(b[0]), "r"(b[1]));
}

// ---------------------------------------------------------------------------
// Kernel 1: embedding gather, K-major: embT[b][l][e] = embed_w[x[b][l]][e]
// ---------------------------------------------------------------------------
__global__ void embed_kernel(const int* __restrict__ x,
                             const float* __restrict__ embed_w)
{
    int b = blockIdx.y;
    int l = blockIdx.x * 8 + (threadIdx.x >> 5);
    int q = threadIdx.x & 31;
    int xi = x[b * L_ + l];
    float4 v = ((const float4*)(embed_w + (size_t)xi * E_))[q];
    ((float4*)(g_embT + ((size_t)b * L_ + l) * E_))[q] = v;
}

// ---------------------------------------------------------------------------
// Kernel 2: transpose conv_w (F,E,3) -> wT[kw][f][e]
// ---------------------------------------------------------------------------
__global__ void wtrans_kernel(const float* __restrict__ conv_w)
{
    int i = blockIdx.x * 256 + threadIdx.x;
    if (i < F_ * E_) {
        int f = i / E_, e = i % E_;
        #pragma unroll
        for (int kw = 0; kw < 3; kw++)
            g_wT[((size_t)kw * F_ + f) * E_ + e] = conv_w[((size_t)f * E_ + e) * 3 + kw];
    }
}

// ---------------------------------------------------------------------------
// Kernel 3/4: tf32 mma.sync GEMM, C[128,128] tile, 256 threads (8 warps).
// Warp grid 4(M) x 2(N), warp tile 32x64, m16n8k8 fragments.
// mode 0 (conv): C[l, f]  = sum_kw sum_e embT[l+kw-1, e] * wT[kw][f][e]
//                K = 3*128 (12 chunks), +bias, relu -> g_hcT[b][l][f]
// mode 1 (attn): C[m, l]  = W[m,:] . hcT[l,:]   K = 256 (8 chunks) -> g_st
// ---------------------------------------------------------------------------
__global__ __launch_bounds__(256, 2)
void mma_gemm_kernel(const float* __restrict__ A0, const float* __restrict__ A1,
                     const float* __restrict__ bias, int mode)
{
    __shared__ unsigned As[BM][36];
    __shared__ unsigned Bs[BN][36];

    int tid  = threadIdx.x;
    int wid  = tid >> 5, lane = tid & 31;
    int g    = lane >> 2, tig = lane & 3;
    int wm   = wid >> 1,  wn  = wid & 1;       // warp coords: 4 x 2
    int b    = blockIdx.z;

    int m0, n0, nchunks;
    if (mode == 0) { m0 = blockIdx.x * BM; n0 = blockIdx.y * BN; nchunks = 12; }
    else           { m0 = blockIdx.y * BM; n0 = blockIdx.x * BN; nchunks = 8;  }

    // loader mapping: 2 threads per 32-float row-chunk
    int lrow = tid >> 1;
    int lcol = (tid & 1) * 16;

    float d[2][8][4];
    #pragma unroll
    for (int mi = 0; mi < 2; mi++)
        #pragma unroll
        for (int ni = 0; ni < 8; ni++)
            #pragma unroll
            for (int q = 0; q < 4; q++) d[mi][ni][q] = 0.0f;

    for (int c = 0; c < nchunks; c++) {
        // ---------------- load A+B chunk into SMEM (tf32-converted) --------
        const float* ap = nullptr;
        const float* bp = nullptr;
        bool avalid = true;

        if (mode == 0) {
            int kw = c >> 2, ks = c & 3;
            int lsrc = m0 + lrow + kw - 1;
            avalid = (lsrc >= 0 && lsrc < L_);
            if (avalid) ap = g_embT + ((size_t)b * L_ + lsrc) * E_ + ks * BKC + lcol;
            bp = g_wT + ((size_t)kw * F_ + n0 + lrow) * E_ + ks * BKC + lcol;
        } else {
            int m = m0 + lrow;
            if (m < Y_)          ap = A0 + (size_t)m * F_ + c * BKC + lcol;
            else if (m < 2 * Y_) ap = A1 + (size_t)(m - Y_) * F_ + c * BKC + lcol;
            else                 avalid = false;
            bp = g_hcT + ((size_t)b * L_ + n0 + lrow) * F_ + c * BKC + lcol;
        }

        __syncthreads();   // protect SMEM from prior iteration's readers
        #pragma unroll
        for (int j = 0; j < 4; j++) {
            float4 va = avalid ? ((const float4*)ap)[j] : make_float4(0.f, 0.f, 0.f, 0.f);
            float4 vb = ((const float4*)bp)[j];
            unsigned* da = &As[lrow][lcol + j * 4];
            unsigned* db = &Bs[lrow][lcol + j * 4];
            da[0] = to_tf32(va.x); da[1] = to_tf32(va.y);
            da[2] = to_tf32(va.z); da[3] = to_tf32(va.w);
            db[0] = to_tf32(vb.x); db[1] = to_tf32(vb.y);
            db[2] = to_tf32(vb.z); db[3] = to_tf32(vb.w);
        }
        __syncthreads();

        // ---------------- compute: 4 k-steps of 8 -------------------------
        #pragma unroll
        for (int ks = 0; ks < 4; ks++) {
            int k8 = ks * 8;
            unsigned af[2][4];
            #pragma unroll
            for (int mi = 0; mi < 2; mi++) {
                int r = wm * 32 + mi * 16 + g;
                af[mi][0] = As[r][k8 + tig];
                af[mi][1] = As[r + 8][k8 + tig];
                af[mi][2] = As[r][k8 + tig + 4];
                af[mi][3] = As[r + 8][k8 + tig + 4];
            }
            unsigned bf[8][2];
            #pragma unroll
            for (int ni = 0; ni < 8; ni++) {
                int nb = wn * 64 + ni * 8 + g;
                bf[ni][0] = Bs[nb][k8 + tig];
                bf[ni][1] = Bs[nb][k8 + tig + 4];
            }
            #pragma unroll
            for (int mi = 0; mi < 2; mi++)
                #pragma unroll
                for (int ni = 0; ni < 8; ni++)
                    mma_tf32(d[mi][ni], af[mi], bf[ni]);
        }
    }

    // ---------------- epilogue ---------------------------------------------
    #pragma unroll
    for (int mi = 0; mi < 2; mi++) {
        int row = m0 + wm * 32 + mi * 16 + g;
        #pragma unroll
        for (int ni = 0; ni < 8; ni++) {
            int col = n0 + wn * 64 + ni * 8 + tig * 2;
            if (mode == 0) {
                float b0 = bias[col], b1 = bias[col + 1];
                float* p0 = g_hcT + ((size_t)b * L_ + row) * F_ + col;
                float* p1 = g_hcT + ((size_t)b * L_ + row + 8) * F_ + col;
                float2 v0 = make_float2(fmaxf(d[mi][ni][0] + b0, 0.f),
                                        fmaxf(d[mi][ni][1] + b1, 0.f));
                float2 v1 = make_float2(fmaxf(d[mi][ni][2] + b0, 0.f),
                                        fmaxf(d[mi][ni][3] + b1, 0.f));
                *(float2*)p0 = v0;
                *(float2*)p1 = v1;
            } else {
                float* p0 = g_st + ((size_t)b * MP_ + row) * L_ + col;
                float* p1 = g_st + ((size_t)b * MP_ + row + 8) * L_ + col;
                *(float2*)p0 = make_float2(d[mi][ni][0], d[mi][ni][1]);
                *(float2*)p1 = make_float2(d[mi][ni][2], d[mi][ni][3]);
            }
        }
    }
}

// ---------------------------------------------------------------------------
// Kernel 5: per-(b,y) online softmax over L + weighted sum of t -> logit.
// ---------------------------------------------------------------------------
__global__ void attn_reduce_kernel(const float* __restrict__ fc_b,
                                   float* __restrict__ out_logit)
{
    int y = blockIdx.x;
    int b = blockIdx.y;
    const float* s = g_st + ((size_t)b * MP_ + y) * L_;
    const float* t = g_st + ((size_t)b * MP_ + Y_ + y) * L_;

    float m = -1e30f, Z = 0.0f, S = 0.0f;
    for (int l = threadIdx.x; l < L_; l += blockDim.x) {
        float sv = s[l], tv = t[l];
        if (sv > m) {
            float r = expf(m - sv);
            Z *= r; S *= r; m = sv;
        }
        float e = expf(sv - m);
        Z += e; S += e * tv;
    }
    #pragma unroll
    for (int off = 16; off; off >>= 1) {
        float m2 = __shfl_xor_sync(0xFFFFFFFFu, m, off);
        float Z2 = __shfl_xor_sync(0xFFFFFFFFu, Z, off);
        float S2 = __shfl_xor_sync(0xFFFFFFFFu, S, off);
        float mn = fmaxf(m, m2);
        float r1 = expf(m - mn), r2 = expf(m2 - mn);
        Z = Z * r1 + Z2 * r2;
        S = S * r1 + S2 * r2;
        m = mn;
    }
    __shared__ float sm[8], sz[8], ss[8];
    int lane = threadIdx.x & 31, w = threadIdx.x >> 5;
    if (lane == 0) { sm[w] = m; sz[w] = Z; ss[w] = S; }
    __syncthreads();
    if (threadIdx.x == 0) {
        m = sm[0]; Z = sz[0]; S = ss[0];
        int nw = blockDim.x >> 5;
        for (int i = 1; i < nw; i++) {
            float mn = fmaxf(m, sm[i]);
            float r1 = expf(m - mn), r2 = expf(sm[i] - mn);
            Z = Z * r1 + sz[i] * r2;
            S = S * r1 + ss[i] * r2;
            m = mn;
        }
        out_logit[b * Y_ + y] = S / Z + fc_b[y];
    }
}

// ---------------------------------------------------------------------------
// Kernel 6: cross-entropy loss
// ---------------------------------------------------------------------------
__global__ void loss_kernel(const float* __restrict__ logit,
                            const int* __restrict__ target,
                            float* __restrict__ loss_out)
{
    __shared__ float red[256];
    int tid = threadIdx.x;
    float total = 0.0f;
    for (int b = 0; b < B_; b++) {
        const float* lr = logit + b * Y_;
        float mx = -1e30f;
        for (int i = tid; i < Y_; i += 256) mx = fmaxf(mx, lr[i]);
        red[tid] = mx; __syncthreads();
        for (int s = 128; s; s >>= 1) {
            if (tid < s) red[tid] = fmaxf(red[tid], red[tid + s]);
            __syncthreads();
        }
        mx = red[0]; __syncthreads();

        float se = 0.0f;
        for (int i = tid; i < Y_; i += 256) se += expf(lr[i] - mx);
        red[tid] = se; __syncthreads();
        for (int s = 128; s; s >>= 1) {
            if (tid < s) red[tid] += red[tid + s];
            __syncthreads();
        }
        if (tid == 0) {
            float lp = lr[target[b]] - mx - logf(red[0]);
            total += -lp;
        }
        __syncthreads();
    }
    if (tid == 0) loss_out[0] = total / (float)B_;
}

// ---------------------------------------------------------------------------
extern "C" void kernel_launch(void* const* d_in, const int* in_sizes, int n_in,
                              void* d_out, int out_size)
{
    const int*   x       = (const int*)  d_in[0];
    const int*   target  = (const int*)  d_in[1];
    const float* embed_w = (const float*)d_in[2];
    const float* conv_w  = (const float*)d_in[3];
    const float* conv_b  = (const float*)d_in[4];
    const float* U_w     = (const float*)d_in[5];
    const float* fc_w    = (const float*)d_in[6];
    const float* fc_b    = (const float*)d_in[7];
    float* out = (float*)d_out;   // [0..15999] logits, [16000] loss

    // 1) embedding gather + conv_w transpose
    embed_kernel<<<dim3(L_ / 8, B_), 256>>>(x, embed_w);
    wtrans_kernel<<<(F_ * E_ + 255) / 256, 256>>>(conv_w);

    // 2) conv as 3 shifted K=128 GEMMs: hcT = relu(sum_kw embT(shift) @ wT[kw]^T + b)
    mma_gemm_kernel<<<dim3(L_ / BM, F_ / BN, B_), 256>>>(
        nullptr, nullptr, conv_b, /*mode=*/0);

    // 3) attn GEMM: st[b][m][l] = [U_w;fc_w] . hcT^T
    mma_gemm_kernel<<<dim3(L_ / BN, MP_ / BM, B_), 256>>>(
        U_w, fc_w, nullptr, /*mode=*/1);

    // 4) softmax-attend reduction -> logits
    attn_reduce_kernel<<<dim3(Y_, B_), 256>>>(fc_b, out);

    // 5) cross-entropy loss
    loss_kernel<<<1, 256>>>(out, target, out + B_ * Y_);
}